// round 1
// baseline (speedup 1.0000x reference)
#include <cuda_runtime.h>
#include <math.h>

// ---------------- problem constants ----------------
#define BQ   8
#define LQ   128
#define TSEQ 384          // 3 * L tokens per batch
#define MTOK 3072         // BQ * TSEQ
#define DM   256          // d_model
#define DI   512          // d_inner
#define DS   16           // d_state
#define RK   16           // dt_rank
#define NL   4

// ---------------- scratch (device globals; no allocation allowed) ----------------
__device__ float g_u  [MTOK * DM];
__device__ float g_res[MTOK * DM];
__device__ float g_xn [MTOK * DM];
__device__ float g_xz [MTOK * 2 * DI];
__device__ float g_xc [MTOK * DI];
__device__ float g_proj[MTOK * 48];
__device__ float g_dt [MTOK * DI];
__device__ float g_y  [MTOK * DI];
__device__ float g_fin[MTOK * DM];

// ---------------- embeddings + interleave -> u ----------------
__global__ void k_embed(const float* __restrict__ states,
                        const float* __restrict__ actions,
                        const float* __restrict__ goal,
                        const int*   __restrict__ timesteps,
                        const float* __restrict__ te_W,
                        const float* __restrict__ se_W, const float* __restrict__ se_b,
                        const float* __restrict__ ge_W, const float* __restrict__ ge_b,
                        const float* __restrict__ ae_W, const float* __restrict__ ae_b)
{
    int m = blockIdx.x;          // token 0..3071
    int e = threadIdx.x;         // 0..255
    int b = m / TSEQ, t = m % TSEQ;
    int slot = t % 3, l = t / 3;

    const float *inp, *Wm, *bi; int dim;
    if (slot == 0)      { inp = goal;    Wm = ge_W; bi = ge_b; dim = 6; }
    else if (slot == 1) { inp = states;  Wm = se_W; bi = se_b; dim = 6; }
    else                { inp = actions; Wm = ae_W; bi = ae_b; dim = 3; }

    float v = bi[e];
    const float* ip = inp + (size_t)(b * LQ + l) * dim;
    #pragma unroll 6
    for (int i = 0; i < dim; i++) v += ip[i] * Wm[i * DM + e];

    int ts = timesteps[b * LQ + l];
    v += te_W[(size_t)ts * DM + e];
    g_u[(size_t)m * DM + e] = v;
}

// ---------------- rmsnorm (one block per row of 256) ----------------
__global__ void k_rmsnorm(const float* __restrict__ in,
                          const float* __restrict__ w,
                          float* __restrict__ out)
{
    int m = blockIdx.x, e = threadIdx.x;
    float x = in[(size_t)m * DM + e];
    float s = x * x;
    #pragma unroll
    for (int o = 16; o > 0; o >>= 1) s += __shfl_down_sync(0xffffffffu, s, o);
    __shared__ float ws[8];
    if ((e & 31) == 0) ws[e >> 5] = s;
    __syncthreads();
    if (e < 8) {
        float t = ws[e];
        #pragma unroll
        for (int o = 4; o > 0; o >>= 1) t += __shfl_down_sync(0xffu, t, o);
        if (e == 0) ws[0] = t;
    }
    __syncthreads();
    float scale = rsqrtf(ws[0] * (1.0f / DM) + 1e-5f);
    out[(size_t)m * DM + e] = x * scale * w[e];
}

// ---------------- tiled SGEMM: C[M,N] = A[M,K] @ W[K,N] (+epilogue) ----------------
// EPI: 0 = store (+bias if non-null), 1 = accumulate into C, 2 = softplus(v + bias)
template<int EPI>
__global__ __launch_bounds__(256)
void k_gemm64(const float* __restrict__ A, int lda,
              const float* __restrict__ W, int N, int K,
              const float* __restrict__ bias,
              float* __restrict__ C, int ldc)
{
    __shared__ float As[16][64];   // transposed A tile
    __shared__ float Ws[16][68];

    int tid = threadIdx.x;
    int tx = tid & 15, ty = tid >> 4;
    int bm = blockIdx.y * 64, bn = blockIdx.x * 64;

    float acc[4][4] = {};

    int arow = tid >> 2;           // 0..63
    int acol = (tid & 3) << 2;     // 0,4,8,12

    for (int k0 = 0; k0 < K; k0 += 16) {
        const float* Ap = A + (size_t)(bm + arow) * lda + k0 + acol;
        #pragma unroll
        for (int i = 0; i < 4; i++) As[acol + i][arow] = Ap[i];

        const float* Wp = W + (size_t)(k0 + ty) * N + bn + tx * 4;
        #pragma unroll
        for (int i = 0; i < 4; i++) {
            int c = bn + tx * 4 + i;
            Ws[ty][tx * 4 + i] = (c < N) ? Wp[i] : 0.f;
        }
        __syncthreads();

        #pragma unroll
        for (int k = 0; k < 16; k++) {
            float a[4], w[4];
            #pragma unroll
            for (int i = 0; i < 4; i++) a[i] = As[k][ty * 4 + i];
            #pragma unroll
            for (int j = 0; j < 4; j++) w[j] = Ws[k][tx * 4 + j];
            #pragma unroll
            for (int i = 0; i < 4; i++)
                #pragma unroll
                for (int j = 0; j < 4; j++) acc[i][j] += a[i] * w[j];
        }
        __syncthreads();
    }

    #pragma unroll
    for (int i = 0; i < 4; i++) {
        int row = bm + ty * 4 + i;
        #pragma unroll
        for (int j = 0; j < 4; j++) {
            int col = bn + tx * 4 + j;
            if (col < N) {
                float v = acc[i][j];
                if (EPI == 0) {
                    if (bias) v += bias[col];
                    C[(size_t)row * ldc + col] = v;
                } else if (EPI == 1) {
                    C[(size_t)row * ldc + col] += v;
                } else {  // softplus epilogue for dt
                    v += bias[col];
                    v = (v > 20.f) ? v : log1pf(__expf(v));
                    C[(size_t)row * ldc + col] = v;
                }
            }
        }
    }
}

// ---------------- causal depthwise conv (k=4) + silu ----------------
__global__ void k_conv(const float* __restrict__ cw, const float* __restrict__ cb)
{
    int idx = blockIdx.x * blockDim.x + threadIdx.x;
    if (idx >= MTOK * DI) return;
    int m = idx / DI, d = idx % DI;
    int b = m / TSEQ, t = m % TSEQ;
    float acc = cb[d];
    const float* w = cw + d * 4;
    #pragma unroll
    for (int k = 0; k < 4; k++) {
        int tt = t - 3 + k;
        if (tt >= 0) acc += w[k] * g_xz[((size_t)(b * TSEQ + tt)) * (2 * DI) + d];
    }
    acc = acc / (1.f + __expf(-acc));      // silu
    g_xc[idx] = acc;
}

// ---------------- selective scan (thread per (b,d), 16 states in regs) ----------------
__global__ __launch_bounds__(128)
void k_scan(const float* __restrict__ A_log, const float* __restrict__ Dp)
{
    int b = blockIdx.x >> 2;
    int d = ((blockIdx.x & 3) << 7) + threadIdx.x;   // 0..511

    float A[16], h[16];
    #pragma unroll
    for (int n = 0; n < 16; n++) {
        A[n] = -__expf(A_log[d * 16 + n]);
        h[n] = 0.f;
    }
    float Dpl = Dp[d];

    __shared__ float sBC[8][32];   // 8 steps of (B[16], C[16]) for this batch

    for (int t0 = 0; t0 < TSEQ; t0 += 8) {
        __syncthreads();
        int i0 = threadIdx.x * 2;
        #pragma unroll
        for (int i = 0; i < 2; i++) {
            int idx = i0 + i; int st = idx >> 5, j = idx & 31;
            sBC[st][j] = g_proj[((size_t)(b * TSEQ + t0 + st)) * 48 + 16 + j];
        }
        __syncthreads();

        #pragma unroll
        for (int tt = 0; tt < 8; tt++) {
            int m = b * TSEQ + t0 + tt;
            float dt  = g_dt[(size_t)m * DI + d];
            float x   = g_xc[(size_t)m * DI + d];
            float dtx = dt * x;
            float y = 0.f;
            #pragma unroll
            for (int n = 0; n < 16; n++) {
                float dA = __expf(dt * A[n]);
                h[n] = dA * h[n] + dtx * sBC[tt][n];
                y += h[n] * sBC[tt][16 + n];
            }
            float z = g_xz[(size_t)m * (2 * DI) + DI + d];
            float o = (y + x * Dpl) * (z / (1.f + __expf(-z)));
            g_y[(size_t)m * DI + d] = o;
        }
    }
}

// ---------------- output heads ----------------
__global__ void k_heads(const float* __restrict__ ps_W, const float* __restrict__ ps_b,
                        const float* __restrict__ pa_W, const float* __restrict__ pa_b,
                        float* __restrict__ out)
{
    int idx = blockIdx.x * blockDim.x + threadIdx.x;
    if (idx >= 6144 + 3072) return;
    if (idx < 6144) {
        // state_preds from action-slot tokens (slot 2)
        int j = idx % 6; int l = (idx / 6) % LQ; int b = idx / (6 * LQ);
        int m = b * TSEQ + l * 3 + 2;
        float acc = ps_b[j];
        const float* f = g_fin + (size_t)m * DM;
        #pragma unroll 8
        for (int e = 0; e < DM; e++) acc += f[e] * ps_W[e * 6 + j];
        out[idx] = acc;
    } else {
        // action_preds from state-slot tokens (slot 1), tanh
        int k = idx - 6144;
        int j = k % 3; int l = (k / 3) % LQ; int b = k / (3 * LQ);
        int m = b * TSEQ + l * 3 + 1;
        float acc = pa_b[j];
        const float* f = g_fin + (size_t)m * DM;
        #pragma unroll 8
        for (int e = 0; e < DM; e++) acc += f[e] * pa_W[e * 3 + j];
        out[idx] = tanhf(acc);
    }
}

// ---------------- launch ----------------
extern "C" void kernel_launch(void* const* d_in, const int* in_sizes, int n_in,
                              void* d_out, int out_size)
{
    const float* states    = (const float*)d_in[0];
    const float* actions   = (const float*)d_in[1];
    const float* goal      = (const float*)d_in[2];
    const int*   timesteps = (const int*)  d_in[3];
    const float* te_W      = (const float*)d_in[4];
    const float* se_W      = (const float*)d_in[5];
    const float* se_b      = (const float*)d_in[6];
    const float* ge_W      = (const float*)d_in[7];
    const float* ge_b      = (const float*)d_in[8];
    const float* ae_W      = (const float*)d_in[9];
    const float* ae_b      = (const float*)d_in[10];
    const float* bb_in_W   = (const float*)d_in[11];
    const float* bb_in_b   = (const float*)d_in[12];
    const float* norm_w    = (const float*)d_in[13];
    const float* in_proj_W = (const float*)d_in[14];
    const float* conv_w    = (const float*)d_in[15];
    const float* conv_b    = (const float*)d_in[16];
    const float* xproj_W   = (const float*)d_in[17];
    const float* dt_W      = (const float*)d_in[18];
    const float* dt_b      = (const float*)d_in[19];
    const float* A_log     = (const float*)d_in[20];
    const float* Dp        = (const float*)d_in[21];
    const float* out_W     = (const float*)d_in[22];
    const float* fnorm_w   = (const float*)d_in[23];
    const float* ps_W      = (const float*)d_in[24];
    const float* ps_b      = (const float*)d_in[25];
    const float* pa_W      = (const float*)d_in[26];
    const float* pa_b      = (const float*)d_in[27];
    float* out = (float*)d_out;

    float *pu, *pres, *pxn, *pxz, *pxc, *pproj, *pdt, *py, *pfin;
    cudaGetSymbolAddress((void**)&pu,    g_u);
    cudaGetSymbolAddress((void**)&pres,  g_res);
    cudaGetSymbolAddress((void**)&pxn,   g_xn);
    cudaGetSymbolAddress((void**)&pxz,   g_xz);
    cudaGetSymbolAddress((void**)&pxc,   g_xc);
    cudaGetSymbolAddress((void**)&pproj, g_proj);
    cudaGetSymbolAddress((void**)&pdt,   g_dt);
    cudaGetSymbolAddress((void**)&py,    g_y);
    cudaGetSymbolAddress((void**)&pfin,  g_fin);

    // 1) embeddings -> u
    k_embed<<<MTOK, DM>>>(states, actions, goal, timesteps, te_W,
                          se_W, se_b, ge_W, ge_b, ae_W, ae_b);

    // 2) residual = u @ bb_in_W + bb_in_b   (3072 x 256 x 256)
    k_gemm64<0><<<dim3(DM / 64, MTOK / 64), 256>>>(pu, DM, bb_in_W, DM, DM,
                                                   bb_in_b, pres, DM);

    // 3) mamba layers
    for (int i = 0; i < NL; i++) {
        const float* inW  = in_proj_W + (size_t)i * DM * 2 * DI;
        const float* cw   = conv_w    + (size_t)i * DI * 4;
        const float* cb   = conv_b    + (size_t)i * DI;
        const float* xpW  = xproj_W   + (size_t)i * DI * 48;
        const float* dtW  = dt_W      + (size_t)i * RK * DI;
        const float* dtb  = dt_b      + (size_t)i * DI;
        const float* Al   = A_log     + (size_t)i * DI * DS;
        const float* Dpi  = Dp        + (size_t)i * DI;
        const float* oW   = out_W     + (size_t)i * DI * DM;
        const float* nw   = norm_w    + (size_t)i * DM;

        k_rmsnorm<<<MTOK, DM>>>(pres, nw, pxn);

        // xz = xn @ in_W   (3072 x 1024 x 256)
        k_gemm64<0><<<dim3(2 * DI / 64, MTOK / 64), 256>>>(pxn, DM, inW, 2 * DI, DM,
                                                           nullptr, pxz, 2 * DI);

        // causal depthwise conv + silu -> xc
        k_conv<<<(MTOK * DI) / 256, 256>>>(cw, cb);

        // proj = xc @ xproj_W   (3072 x 48 x 512)
        k_gemm64<0><<<dim3(1, MTOK / 64), 256>>>(pxc, DI, xpW, 48, DI,
                                                 nullptr, pproj, 48);

        // dt = softplus(proj[:, :16] @ dt_W + dt_b)   (3072 x 512 x 16)
        k_gemm64<2><<<dim3(DI / 64, MTOK / 64), 256>>>(pproj, 48, dtW, DI, RK,
                                                       dtb, pdt, DI);

        // selective scan + D skip + silu(z) gate -> y
        k_scan<<<BQ * 4, 128>>>(Al, Dpi);

        // residual += y @ out_W   (3072 x 256 x 512)
        k_gemm64<1><<<dim3(DM / 64, MTOK / 64), 256>>>(py, DI, oW, DM, DI,
                                                       nullptr, pres, DM);
    }

    // 4) final norm + heads
    k_rmsnorm<<<MTOK, DM>>>(pres, fnorm_w, pfin);
    k_heads<<<(9216 + 255) / 256, 256>>>(ps_W, ps_b, pa_W, pa_b, out);
}

// round 2
// speedup vs baseline: 1.1237x; 1.1237x over previous
#include <cuda_runtime.h>
#include <math.h>

// ---------------- problem constants ----------------
#define BQ   8
#define LQ   128
#define TSEQ 384          // 3 * L tokens per batch
#define MTOK 3072         // BQ * TSEQ
#define DM   256          // d_model
#define DI   512          // d_inner
#define DS   16           // d_state
#define RK   16           // dt_rank
#define NL   4

// ---------------- scratch (device globals; no allocation allowed) ----------------
__device__ float g_u  [MTOK * DM];
__device__ float g_res[MTOK * DM];
__device__ float g_rs [MTOK];          // per-row rmsnorm scales
__device__ float g_xz [MTOK * 2 * DI];
__device__ float g_xc [MTOK * DI];
__device__ float g_proj[MTOK * 48];
__device__ float g_dt [MTOK * DI];
__device__ float g_y  [MTOK * DI];
__device__ float g_fin[MTOK * DM];

// ---------------- embeddings + interleave -> u ----------------
__global__ void k_embed(const float* __restrict__ states,
                        const float* __restrict__ actions,
                        const float* __restrict__ goal,
                        const int*   __restrict__ timesteps,
                        const float* __restrict__ te_W,
                        const float* __restrict__ se_W, const float* __restrict__ se_b,
                        const float* __restrict__ ge_W, const float* __restrict__ ge_b,
                        const float* __restrict__ ae_W, const float* __restrict__ ae_b)
{
    int m = blockIdx.x;          // token 0..3071
    int e = threadIdx.x;         // 0..255
    int b = m / TSEQ, t = m % TSEQ;
    int slot = t % 3, l = t / 3;

    const float *inp, *Wm, *bi; int dim;
    if (slot == 0)      { inp = goal;    Wm = ge_W; bi = ge_b; dim = 6; }
    else if (slot == 1) { inp = states;  Wm = se_W; bi = se_b; dim = 6; }
    else                { inp = actions; Wm = ae_W; bi = ae_b; dim = 3; }

    float v = bi[e];
    const float* ip = inp + (size_t)(b * LQ + l) * dim;
    #pragma unroll 6
    for (int i = 0; i < dim; i++) v += ip[i] * Wm[i * DM + e];

    int ts = timesteps[b * LQ + l];
    v += te_W[(size_t)ts * DM + e];
    g_u[(size_t)m * DM + e] = v;
}

// ---------------- per-row rmsnorm scale: rs[m] = rsqrt(mean(x^2)+eps) ----------------
__global__ void k_rowscale(const float* __restrict__ in, float* __restrict__ rs)
{
    int warp = blockIdx.x * 8 + (threadIdx.x >> 5);
    int lane = threadIdx.x & 31;
    const float4* p = (const float4*)(in + (size_t)warp * DM);
    float s = 0.f;
    #pragma unroll
    for (int i = lane; i < DM / 4; i += 32) {
        float4 v = p[i];
        s += v.x * v.x + v.y * v.y + v.z * v.z + v.w * v.w;
    }
    #pragma unroll
    for (int o = 16; o > 0; o >>= 1) s += __shfl_down_sync(0xffffffffu, s, o);
    if (lane == 0) rs[warp] = rsqrtf(s * (1.0f / DM) + 1e-5f);
}

// ---------------- full rmsnorm (final norm only) ----------------
__global__ void k_rmsnorm(const float* __restrict__ in,
                          const float* __restrict__ w,
                          float* __restrict__ out)
{
    int m = blockIdx.x, e = threadIdx.x;
    float x = in[(size_t)m * DM + e];
    float s = x * x;
    #pragma unroll
    for (int o = 16; o > 0; o >>= 1) s += __shfl_down_sync(0xffffffffu, s, o);
    __shared__ float ws[8];
    if ((e & 31) == 0) ws[e >> 5] = s;
    __syncthreads();
    if (e < 8) {
        float t = ws[e];
        #pragma unroll
        for (int o = 4; o > 0; o >>= 1) t += __shfl_down_sync(0xffu, t, o);
        if (e == 0) ws[0] = t;
    }
    __syncthreads();
    float scale = rsqrtf(ws[0] * (1.0f / DM) + 1e-5f);
    out[(size_t)m * DM + e] = x * scale * w[e];
}

// ---------------- 128x64x16 SGEMM, 8x4 per thread, float4 everywhere ----------------
// C[M,N] = A'[M,K] @ W[K,N]  where A' = A (NORM=false) or A * rs[m] * nw[k] (NORM=true)
// EPI: 0 = store (+bias if non-null), 1 = accumulate into C, 2 = softplus(v + bias)
// Requires: M%128==0, N%64==0, K%16==0, lda%4==0, row byte-offsets 16B-aligned.
template<int EPI, bool NORM>
__global__ __launch_bounds__(256)
void k_gemm128(const float* __restrict__ A, int lda,
               const float* __restrict__ W, int N, int K,
               const float* __restrict__ bias,
               const float* __restrict__ rs,
               const float* __restrict__ nw,
               float* __restrict__ C, int ldc)
{
    __shared__ float As[16][128];
    __shared__ float Ws[16][68];

    int tid = threadIdx.x;
    int bm = blockIdx.y * 128, bn = blockIdx.x * 64;
    int tx = tid & 15;       // col group -> cols tx*4 .. +4
    int ty = tid >> 4;       // row group -> rows ty*8 .. +8

    // A-tile cooperative load mapping (2 x float4 per thread)
    int arow = tid >> 2;            // 0..63
    int acol = (tid & 3) * 4;       // 0,4,8,12
    // W-tile mapping (1 x float4 per thread)
    int wk = tid >> 4, wn = (tid & 15) * 4;

    float acc[8][4] = {};

    for (int k0 = 0; k0 < K; k0 += 16) {
        #pragma unroll
        for (int rr = 0; rr < 2; rr++) {
            int r = arow + rr * 64;
            float4 v = *(const float4*)(A + (size_t)(bm + r) * lda + k0 + acol);
            if (NORM) {
                float s = rs[bm + r];
                v.x *= s * nw[k0 + acol + 0];
                v.y *= s * nw[k0 + acol + 1];
                v.z *= s * nw[k0 + acol + 2];
                v.w *= s * nw[k0 + acol + 3];
            }
            As[acol + 0][r] = v.x;
            As[acol + 1][r] = v.y;
            As[acol + 2][r] = v.z;
            As[acol + 3][r] = v.w;
        }
        *(float4*)&Ws[wk][wn] = *(const float4*)(W + (size_t)(k0 + wk) * N + bn + wn);
        __syncthreads();

        #pragma unroll
        for (int k = 0; k < 16; k++) {
            float4 a0 = *(const float4*)&As[k][ty * 8];
            float4 a1 = *(const float4*)&As[k][ty * 8 + 4];
            float4 w0 = *(const float4*)&Ws[k][tx * 4];
            float a[8] = {a0.x, a0.y, a0.z, a0.w, a1.x, a1.y, a1.z, a1.w};
            float w[4] = {w0.x, w0.y, w0.z, w0.w};
            #pragma unroll
            for (int i = 0; i < 8; i++)
                #pragma unroll
                for (int j = 0; j < 4; j++) acc[i][j] += a[i] * w[j];
        }
        __syncthreads();
    }

    #pragma unroll
    for (int i = 0; i < 8; i++) {
        int row = bm + ty * 8 + i;
        #pragma unroll
        for (int j = 0; j < 4; j++) {
            int col = bn + tx * 4 + j;
            float v = acc[i][j];
            if (EPI == 0) {
                if (bias) v += bias[col];
                C[(size_t)row * ldc + col] = v;
            } else if (EPI == 1) {
                C[(size_t)row * ldc + col] += v;
            } else {
                v += bias[col];
                v = (v > 20.f) ? v : log1pf(__expf(v));
                C[(size_t)row * ldc + col] = v;
            }
        }
    }
}

// ---------------- 64x64x16 SGEMM (for N=48 xproj) ----------------
__global__ __launch_bounds__(256)
void k_gemm64(const float* __restrict__ A, int lda,
              const float* __restrict__ W, int N, int K,
              float* __restrict__ C, int ldc)
{
    __shared__ float As[16][64];
    __shared__ float Ws[16][68];

    int tid = threadIdx.x;
    int tx = tid & 15, ty = tid >> 4;
    int bm = blockIdx.y * 64, bn = blockIdx.x * 64;

    float acc[4][4] = {};
    int arow = tid >> 2;
    int acol = (tid & 3) << 2;

    for (int k0 = 0; k0 < K; k0 += 16) {
        float4 v = *(const float4*)(A + (size_t)(bm + arow) * lda + k0 + acol);
        As[acol + 0][arow] = v.x;
        As[acol + 1][arow] = v.y;
        As[acol + 2][arow] = v.z;
        As[acol + 3][arow] = v.w;

        const float* Wp = W + (size_t)(k0 + ty) * N + bn + tx * 4;
        #pragma unroll
        for (int i = 0; i < 4; i++) {
            int c = bn + tx * 4 + i;
            Ws[ty][tx * 4 + i] = (c < N) ? Wp[i] : 0.f;
        }
        __syncthreads();

        #pragma unroll
        for (int k = 0; k < 16; k++) {
            float a[4], w[4];
            #pragma unroll
            for (int i = 0; i < 4; i++) a[i] = As[k][ty * 4 + i];
            #pragma unroll
            for (int j = 0; j < 4; j++) w[j] = Ws[k][tx * 4 + j];
            #pragma unroll
            for (int i = 0; i < 4; i++)
                #pragma unroll
                for (int j = 0; j < 4; j++) acc[i][j] += a[i] * w[j];
        }
        __syncthreads();
    }

    #pragma unroll
    for (int i = 0; i < 4; i++) {
        int row = bm + ty * 4 + i;
        #pragma unroll
        for (int j = 0; j < 4; j++) {
            int col = bn + tx * 4 + j;
            if (col < N) C[(size_t)row * ldc + col] = acc[i][j];
        }
    }
}

// ---------------- causal depthwise conv (k=4) + silu ----------------
__global__ void k_conv(const float* __restrict__ cw, const float* __restrict__ cb)
{
    int idx = blockIdx.x * blockDim.x + threadIdx.x;
    if (idx >= MTOK * DI) return;
    int m = idx / DI, d = idx % DI;
    int b = m / TSEQ, t = m % TSEQ;
    float acc = cb[d];
    const float* w = cw + d * 4;
    #pragma unroll
    for (int k = 0; k < 4; k++) {
        int tt = t - 3 + k;
        if (tt >= 0) acc += w[k] * g_xz[((size_t)(b * TSEQ + tt)) * (2 * DI) + d];
    }
    acc = acc / (1.f + __expf(-acc));      // silu
    g_xc[idx] = acc;
}

// ---------------- selective scan: 64 blocks x 64 threads, 16 states in regs -----
__global__ __launch_bounds__(64)
void k_scan(const float* __restrict__ A_log, const float* __restrict__ Dp)
{
    int b = blockIdx.x >> 3;                          // batch
    int d = ((blockIdx.x & 7) << 6) + threadIdx.x;    // 0..511

    float A[16], h[16];
    #pragma unroll
    for (int n = 0; n < 16; n++) {
        A[n] = -__expf(A_log[d * 16 + n]);
        h[n] = 0.f;
    }
    float Dpl = Dp[d];

    __shared__ float sBC[8][32];   // 8 steps of (B[16], C[16]) for this batch

    for (int t0 = 0; t0 < TSEQ; t0 += 8) {
        __syncthreads();
        int i0 = threadIdx.x * 4;
        #pragma unroll
        for (int i = 0; i < 4; i++) {
            int idx = i0 + i; int st = idx >> 5, j = idx & 31;
            sBC[st][j] = g_proj[((size_t)(b * TSEQ + t0 + st)) * 48 + 16 + j];
        }
        __syncthreads();

        #pragma unroll
        for (int tt = 0; tt < 8; tt++) {
            int m = b * TSEQ + t0 + tt;
            float dt  = g_dt[(size_t)m * DI + d];
            float x   = g_xc[(size_t)m * DI + d];
            float dtx = dt * x;
            float y = 0.f;
            #pragma unroll
            for (int n = 0; n < 16; n++) {
                float dA = __expf(dt * A[n]);
                h[n] = dA * h[n] + dtx * sBC[tt][n];
                y += h[n] * sBC[tt][16 + n];
            }
            float z = g_xz[(size_t)m * (2 * DI) + DI + d];
            float o = (y + x * Dpl) * (z / (1.f + __expf(-z)));
            g_y[(size_t)m * DI + d] = o;
        }
    }
}

// ---------------- output heads ----------------
__global__ void k_heads(const float* __restrict__ ps_W, const float* __restrict__ ps_b,
                        const float* __restrict__ pa_W, const float* __restrict__ pa_b,
                        float* __restrict__ out)
{
    int idx = blockIdx.x * blockDim.x + threadIdx.x;
    if (idx >= 6144 + 3072) return;
    if (idx < 6144) {
        int j = idx % 6; int l = (idx / 6) % LQ; int b = idx / (6 * LQ);
        int m = b * TSEQ + l * 3 + 2;
        float acc = ps_b[j];
        const float* f = g_fin + (size_t)m * DM;
        #pragma unroll 8
        for (int e = 0; e < DM; e++) acc += f[e] * ps_W[e * 6 + j];
        out[idx] = acc;
    } else {
        int k = idx - 6144;
        int j = k % 3; int l = (k / 3) % LQ; int b = k / (3 * LQ);
        int m = b * TSEQ + l * 3 + 1;
        float acc = pa_b[j];
        const float* f = g_fin + (size_t)m * DM;
        #pragma unroll 8
        for (int e = 0; e < DM; e++) acc += f[e] * pa_W[e * 3 + j];
        out[idx] = tanhf(acc);
    }
}

// ---------------- launch ----------------
extern "C" void kernel_launch(void* const* d_in, const int* in_sizes, int n_in,
                              void* d_out, int out_size)
{
    const float* states    = (const float*)d_in[0];
    const float* actions   = (const float*)d_in[1];
    const float* goal      = (const float*)d_in[2];
    const int*   timesteps = (const int*)  d_in[3];
    const float* te_W      = (const float*)d_in[4];
    const float* se_W      = (const float*)d_in[5];
    const float* se_b      = (const float*)d_in[6];
    const float* ge_W      = (const float*)d_in[7];
    const float* ge_b      = (const float*)d_in[8];
    const float* ae_W      = (const float*)d_in[9];
    const float* ae_b      = (const float*)d_in[10];
    const float* bb_in_W   = (const float*)d_in[11];
    const float* bb_in_b   = (const float*)d_in[12];
    const float* norm_w    = (const float*)d_in[13];
    const float* in_proj_W = (const float*)d_in[14];
    const float* conv_w    = (const float*)d_in[15];
    const float* conv_b    = (const float*)d_in[16];
    const float* xproj_W   = (const float*)d_in[17];
    const float* dt_W      = (const float*)d_in[18];
    const float* dt_b      = (const float*)d_in[19];
    const float* A_log     = (const float*)d_in[20];
    const float* Dp        = (const float*)d_in[21];
    const float* out_W     = (const float*)d_in[22];
    const float* fnorm_w   = (const float*)d_in[23];
    const float* ps_W      = (const float*)d_in[24];
    const float* ps_b      = (const float*)d_in[25];
    const float* pa_W      = (const float*)d_in[26];
    const float* pa_b      = (const float*)d_in[27];
    float* out = (float*)d_out;

    float *pu, *pres, *prs, *pxz, *pxc, *pproj, *pdt, *py, *pfin;
    cudaGetSymbolAddress((void**)&pu,    g_u);
    cudaGetSymbolAddress((void**)&pres,  g_res);
    cudaGetSymbolAddress((void**)&prs,   g_rs);
    cudaGetSymbolAddress((void**)&pxz,   g_xz);
    cudaGetSymbolAddress((void**)&pxc,   g_xc);
    cudaGetSymbolAddress((void**)&pproj, g_proj);
    cudaGetSymbolAddress((void**)&pdt,   g_dt);
    cudaGetSymbolAddress((void**)&py,    g_y);
    cudaGetSymbolAddress((void**)&pfin,  g_fin);

    // 1) embeddings -> u
    k_embed<<<MTOK, DM>>>(states, actions, goal, timesteps, te_W,
                          se_W, se_b, ge_W, ge_b, ae_W, ae_b);

    // 2) residual = u @ bb_in_W + bb_in_b   (3072 x 256 x 256)
    k_gemm128<0, false><<<dim3(DM / 64, MTOK / 128), 256>>>(
        pu, DM, bb_in_W, DM, DM, bb_in_b, nullptr, nullptr, pres, DM);

    // 3) mamba layers
    for (int i = 0; i < NL; i++) {
        const float* inW  = in_proj_W + (size_t)i * DM * 2 * DI;
        const float* cw   = conv_w    + (size_t)i * DI * 4;
        const float* cb   = conv_b    + (size_t)i * DI;
        const float* xpW  = xproj_W   + (size_t)i * DI * 48;
        const float* dtW  = dt_W      + (size_t)i * RK * DI;
        const float* dtb  = dt_b      + (size_t)i * DI;
        const float* Al   = A_log     + (size_t)i * DI * DS;
        const float* Dpi  = Dp        + (size_t)i * DI;
        const float* oW   = out_W     + (size_t)i * DI * DM;
        const float* nw   = norm_w    + (size_t)i * DM;

        // rmsnorm row scales
        k_rowscale<<<MTOK / 8, 256>>>(pres, prs);

        // xz = rmsnorm(res) @ in_W   (3072 x 1024 x 256), norm folded into A-load
        k_gemm128<0, true><<<dim3(2 * DI / 64, MTOK / 128), 256>>>(
            pres, DM, inW, 2 * DI, DM, nullptr, prs, nw, pxz, 2 * DI);

        // causal depthwise conv + silu -> xc
        k_conv<<<(MTOK * DI) / 256, 256>>>(cw, cb);

        // proj = xc @ xproj_W   (3072 x 48 x 512)
        k_gemm64<<<dim3(1, MTOK / 64), 256>>>(pxc, DI, xpW, 48, DI, pproj, 48);

        // dt = softplus(proj[:, :16] @ dt_W + dt_b)   (3072 x 512 x 16)
        k_gemm128<2, false><<<dim3(DI / 64, MTOK / 128), 256>>>(
            pproj, 48, dtW, DI, RK, dtb, nullptr, nullptr, pdt, DI);

        // selective scan + D skip + silu(z) gate -> y
        k_scan<<<BQ * 8, 64>>>(Al, Dpi);

        // residual += y @ out_W   (3072 x 256 x 512)
        k_gemm128<1, false><<<dim3(DM / 64, MTOK / 128), 256>>>(
            py, DI, oW, DM, DI, nullptr, nullptr, nullptr, pres, DM);
    }

    // 4) final norm + heads
    k_rmsnorm<<<MTOK, DM>>>(pres, fnorm_w, pfin);
    k_heads<<<(9216 + 255) / 256, 256>>>(ps_W, ps_b, pa_W, pa_b, out);
}